// round 8
// baseline (speedup 1.0000x reference)
#include <cuda_runtime.h>
#include <cstdint>

#define NPTS   500000
#define CCH    128
#define KTAPS  27
#define C4     32
#define C2     64

typedef unsigned long long ull;

// ---------- packed f32x2 helpers (dense FFMA stage 4) ----------
static __device__ __forceinline__ ull fma2(ull a, ull b, ull c) {
    ull d;
    asm("fma.rn.f32x2 %0, %1, %2, %3;" : "=l"(d) : "l"(a), "l"(b), "l"(c));
    return d;
}
static __device__ __forceinline__ ull dup2(float w) {
    ull r;
    asm("mov.b64 %0, {%1, %1};" : "=l"(r) : "f"(w));
    return r;
}
static __device__ __forceinline__ void unpack2(ull v, float& lo, float& hi) {
    asm("mov.b64 {%0, %1}, %2;" : "=f"(lo), "=f"(hi) : "l"(v));
}

// ---------- tf32 / mma / ldmatrix / cp.async helpers ----------
static __device__ __forceinline__ float rna_tf32(float f) {
    unsigned u;
    asm("cvt.rna.tf32.f32 %0, %1;" : "=r"(u) : "f"(f));
    return __uint_as_float(u);
}
static __device__ __forceinline__ void mma_tf32(float* d, const unsigned* a, const unsigned* b) {
    asm volatile(
        "mma.sync.aligned.m16n8k8.row.col.f32.tf32.tf32.f32 "
        "{%0,%1,%2,%3},{%4,%5,%6,%7},{%8,%9},{%0,%1,%2,%3};"
        : "+f"(d[0]), "+f"(d[1]), "+f"(d[2]), "+f"(d[3])
        : "r"(a[0]), "r"(a[1]), "r"(a[2]), "r"(a[3]), "r"(b[0]), "r"(b[1]));
}
static __device__ __forceinline__ void ldsm_x4(unsigned& r0, unsigned& r1,
                                               unsigned& r2, unsigned& r3, unsigned addr) {
    asm volatile("ldmatrix.sync.aligned.m8n8.x4.shared.b16 {%0,%1,%2,%3}, [%4];"
                 : "=r"(r0), "=r"(r1), "=r"(r2), "=r"(r3) : "r"(addr));
}
static __device__ __forceinline__ void cp16(unsigned dst, const void* src, unsigned sz) {
    asm volatile("cp.async.cg.shared.global [%0], [%1], 16, %2;"
                 :: "r"(dst), "l"(src), "r"(sz));
}

// ---------- static scratch ----------
__device__ float g_h0[(size_t)NPTS * C4];   // relu(x@W00+b00), tf32-rounded
__device__ float g_t0[(size_t)NPTS * C4];   // full precision (feeds FFMA stage4)
__device__ float g_h1[(size_t)NPTS * C4];   // tf32-rounded
// fragment-ordered weights: [it][s][lane][nt][2]
__device__ float g_wb00[4   * 4 * 32 * 4 * 2];
__device__ float g_wb01[27  * 4 * 32 * 4 * 2];
__device__ float g_wb10[108 * 4 * 32 * 4 * 2];
__device__ float g_wb11[27  * 4 * 32 * 8 * 2];

// ---------- weight prep: round + reorder into mma-fragment layout ----------
// Wb[(((it*4+s)*32+lane)*NT + nt)*2 + r] = rna(W[k][cc*32 + s*8 + tig + r*4][nt*8 + g])
__global__ void prep_wb(const float* __restrict__ W, float* __restrict__ Wb,
                        int KK, int CIN, int COUT)
{
    const int CHUNKS = CIN / 32;
    const int ITERS  = KK * CHUNKS;
    const int NT     = COUT / 8;
    const int total  = ITERS * 4 * 32 * NT * 2;
    for (int idx = blockIdx.x * blockDim.x + threadIdx.x; idx < total;
         idx += gridDim.x * blockDim.x) {
        const int r    = idx & 1;
        int rest       = idx >> 1;
        const int nt   = rest % NT;  rest /= NT;
        const int lane = rest % 32;  rest /= 32;
        const int s    = rest % 4;   rest /= 4;
        const int it   = rest;
        const int g    = lane >> 2;
        const int tig  = lane & 3;
        const int k    = it / CHUNKS;
        const int cc   = it % CHUNKS;
        const int ci   = cc * 32 + s * 8 + tig + r * 4;
        const int co   = nt * 8 + g;
        Wb[idx] = rna_tf32(W[((size_t)k * CIN + ci) * COUT + co]);
    }
}

// =====================================================================
// Warp-autonomous tf32 conv (dense or gathered). Each warp owns 16 points
// and a private NBUF-deep cp.async ring; B fragments stream from global
// (L1/L2-hot, register double-buffered). NO __syncthreads in the loop.
// =====================================================================
template<int CIN, int COUT, int KK, int NBUF, int WARPS, bool DENSE,
         bool CVT_A, bool RELU, bool RESID, bool ROUND_OUT>
__global__ __launch_bounds__(WARPS * 32)
void conv_wa(const float* __restrict__ fin,
             const int* __restrict__ nbr,
             const int* __restrict__ mask,
             const float* __restrict__ Wb,
             const float* __restrict__ bias,
             float* __restrict__ fout, int out_stride, int out_off,
             const float* __restrict__ resid, int resid_off,
             int npts)
{
    constexpr int CHUNKS  = CIN / 32;
    constexpr int ITERS   = KK * CHUNKS;
    constexpr int NT      = COUT / 8;
    constexpr int BUF_ELE = 16 * 36;       // one warp buffer: 16 rows x 36

    extern __shared__ float smem[];        // WARPS * NBUF * BUF_ELE
    const int tid   = threadIdx.x;
    const int warp  = tid >> 5;
    const int lane  = tid & 31;
    const int wrow0 = blockIdx.x * (WARPS * 16) + warp * 16;

    float* myBuf = smem + warp * NBUF * BUF_ELE;
    const unsigned sb = (unsigned)__cvta_generic_to_shared(myBuf);

    // ---- gather state: 2 lanes per row, 16 ch (64 B) each ----
    const int grow = lane >> 1;
    const int gh   = lane & 1;
    const int p    = wrow0 + grow;
    unsigned mbits = 0;
    const int* nbr_p = nbr;
    if (!DENSE) {
        if (p < npts) {
            const int* mp = mask + (size_t)p * KTAPS;
#pragma unroll
            for (int k = 0; k < KTAPS; ++k) mbits |= (unsigned)(mp[k] != 0) << k;
        }
        nbr_p = nbr + (size_t)p * KTAPS;
    }
    const int pclamp = p < npts ? p : npts - 1;

    auto issue = [&](int it, int buf) {
        const int k  = it / CHUNKS;
        const int cc = it - k * CHUNKS;
        unsigned sz; int j;
        if (DENSE) {
            sz = (p < npts) ? 16u : 0u;
            j  = pclamp;
        } else {
            const unsigned mb = (mbits >> k) & 1u;
            sz = mb ? 16u : 0u;
            j  = mb ? __ldg(nbr_p + k) : 0;
        }
        const float* src = fin + (size_t)j * CIN + cc * 32 + gh * 16;
        const unsigned dst = sb + (buf * BUF_ELE + grow * 36 + gh * 16) * 4;
#pragma unroll
        for (int c = 0; c < 4; ++c)
            cp16(dst + c * 16, src + c * 4, sz);
    };

    // ---- B fragment loader (global, fragment-ordered, coalesced) ----
    auto ldgB = [&](int it, int s, float* dst) {
        const float4* q = (const float4*)(Wb + ((size_t)(it * 4 + s) * 32 + lane) * (NT * 2));
#pragma unroll
        for (int i = 0; i < NT / 2; ++i)
            ((float4*)dst)[i] = __ldg(q + i);
    };

    // ---- A fragment base ----
    const int rowA = (lane & 7) + ((lane >> 3) & 1) * 8;
    const int colA = (lane >> 4) & 1;
    const unsigned a_base = sb + (rowA * 36 + colA * 4) * 4;

    float acc[NT][4];
#pragma unroll
    for (int nt = 0; nt < NT; ++nt)
#pragma unroll
        for (int i = 0; i < 4; ++i) acc[nt][i] = 0.f;

    // ---- prologue: fill NBUF-1 buffers, prefetch B(0,0) ----
#pragma unroll
    for (int i = 0; i < NBUF - 1; ++i) {
        if (i < ITERS) issue(i, i);
        asm volatile("cp.async.commit_group;");
    }
    float Breg[2][NT * 2];
    ldgB(0, 0, Breg[0]);

    for (int it = 0; it < ITERS; ++it) {
        asm volatile("cp.async.wait_group %0;" :: "n"(NBUF - 2));
        __syncwarp();
        {
            const int nx = it + NBUF - 1;
            if (nx < ITERS) issue(nx, nx % NBUF);
            asm volatile("cp.async.commit_group;");
        }
        const unsigned abuf = a_base + (unsigned)((it % NBUF) * BUF_ELE * 4);
#pragma unroll
        for (int s = 0; s < 4; ++s) {
            // prefetch next s-step's B fragments
            {
                const int ni = (s == 3) ? it + 1 : it;
                const int ns = (s + 1) & 3;
                if (ni < ITERS) ldgB(ni, ns, Breg[(s & 1) ^ 1]);
            }
            unsigned A[4];
            ldsm_x4(A[0], A[1], A[2], A[3], abuf + s * 32);
            if (CVT_A) {
#pragma unroll
                for (int i = 0; i < 4; ++i)
                    A[i] = __float_as_uint(rna_tf32(__uint_as_float(A[i])));
            }
            const unsigned* Bc = (const unsigned*)Breg[s & 1];
#pragma unroll
            for (int nt = 0; nt < NT; ++nt)
                mma_tf32(acc[nt], A, Bc + nt * 2);
        }
    }

    // ---- epilogue ----
    const int g   = lane >> 2;
    const int tig = lane & 3;
    float bb[NT][2];
#pragma unroll
    for (int nt = 0; nt < NT; ++nt) {
        bb[nt][0] = bias[nt * 8 + 2 * tig];
        bb[nt][1] = bias[nt * 8 + 2 * tig + 1];
    }
#pragma unroll
    for (int half = 0; half < 2; ++half) {
        const int r = wrow0 + half * 8 + g;
        if (r >= npts) continue;
#pragma unroll
        for (int nt = 0; nt < NT; ++nt) {
            float v0 = acc[nt][half * 2 + 0] + bb[nt][0];
            float v1 = acc[nt][half * 2 + 1] + bb[nt][1];
            if (RELU) { v0 = v0 > 0.f ? v0 : 0.f; v1 = v1 > 0.f ? v1 : 0.f; }
            if (ROUND_OUT) { v0 = rna_tf32(v0); v1 = rna_tf32(v1); }
            if (RESID) {
                const float2 rr = *(const float2*)(resid + (size_t)r * CCH + resid_off + nt * 8 + 2 * tig);
                v0 += rr.x; v1 += rr.y;
            }
            *(float2*)(fout + (size_t)r * out_stride + out_off + nt * 8 + 2 * tig)
                = make_float2(v0, v1);
        }
    }
}

// =====================================================================
// Dense 1x1 FFMA2 kernel (stage 4: 32->64 + residual, full precision).
// =====================================================================
template<int CIN, int COUT, int TP, bool RELU, bool RESID>
__global__ __launch_bounds__(256)
void conv1_kernel(const float* __restrict__ fin,
                  const float* __restrict__ W,
                  const float* __restrict__ bias,
                  float* __restrict__ fout, int out_stride, int out_off,
                  const float* __restrict__ resid, int resid_off,
                  int npts)
{
    constexpr int STR   = TP + 2;
    constexpr int CO_T  = COUT / 16;
    constexpr int PAIRS = TP / 32;
    constexpr int GTPR  = 256 / TP;
    constexpr int GCPT  = CIN / GTPR;

    extern __shared__ float smem[];
    float* sG = smem;
    float* sW = smem + CIN * STR;

    const int tid = threadIdx.x;
    const int n0  = blockIdx.x * TP;

    const int cg  = tid & 15;
    const int pg  = tid >> 4;
    const int co0 = cg * CO_T;
    const int p0  = pg * 2 * PAIRS;

    ull acc[PAIRS][CO_T];
#pragma unroll
    for (int i = 0; i < PAIRS; ++i)
#pragma unroll
        for (int c = 0; c < CO_T; ++c) acc[i][c] = 0ull;

    const int gp  = tid / GTPR;
    const int gh  = tid % GTPR;
    const int gn  = n0 + gp;
    const int ci0 = gh * GCPT;

    constexpr int W4 = CIN * COUT / 4;
    for (int i = tid; i < W4; i += 256) ((float4*)sW)[i] = ((const float4*)W)[i];

    if (gn < npts) {
        const float4* src = (const float4*)(fin + (size_t)gn * CIN + ci0);
#pragma unroll
        for (int c = 0; c < GCPT / 4; ++c) {
            float4 v = src[c];
            int cb = ci0 + c * 4;
            sG[(cb + 0) * STR + gp] = v.x;
            sG[(cb + 1) * STR + gp] = v.y;
            sG[(cb + 2) * STR + gp] = v.z;
            sG[(cb + 3) * STR + gp] = v.w;
        }
    } else {
#pragma unroll
        for (int c = 0; c < GCPT / 4; ++c) {
            int cb = ci0 + c * 4;
            sG[(cb + 0) * STR + gp] = 0.f;
            sG[(cb + 1) * STR + gp] = 0.f;
            sG[(cb + 2) * STR + gp] = 0.f;
            sG[(cb + 3) * STR + gp] = 0.f;
        }
    }
    __syncthreads();

#pragma unroll 4
    for (int ci = 0; ci < CIN; ++ci) {
        ull gg[PAIRS];
        const float* gr = sG + ci * STR + p0;
#pragma unroll
        for (int i = 0; i < PAIRS; ++i) gg[i] = *(const ull*)(gr + 2 * i);

        ull wd[CO_T];
        if (CO_T == 2) {
            float2 wv = *(const float2*)(sW + ci * COUT + co0);
            wd[0] = dup2(wv.x); wd[1] = dup2(wv.y);
        } else {
            float4 wv = *(const float4*)(sW + ci * COUT + co0);
            wd[0] = dup2(wv.x); wd[1] = dup2(wv.y);
            wd[2] = dup2(wv.z); wd[3] = dup2(wv.w);
        }
#pragma unroll
        for (int i = 0; i < PAIRS; ++i)
#pragma unroll
            for (int c = 0; c < CO_T; ++c)
                acc[i][c] = fma2(gg[i], wd[c], acc[i][c]);
    }

    float bb[CO_T];
#pragma unroll
    for (int c = 0; c < CO_T; ++c) bb[c] = bias[co0 + c];

#pragma unroll
    for (int i = 0; i < PAIRS; ++i) {
        float lo[CO_T], hi[CO_T];
#pragma unroll
        for (int c = 0; c < CO_T; ++c) unpack2(acc[i][c], lo[c], hi[c]);
#pragma unroll
        for (int e = 0; e < 2; ++e) {
            const int n = n0 + p0 + 2 * i + e;
            if (n >= npts) continue;
            float v[CO_T];
#pragma unroll
            for (int c = 0; c < CO_T; ++c) {
                v[c] = (e ? hi[c] : lo[c]) + bb[c];
                if (RELU) v[c] = v[c] > 0.f ? v[c] : 0.f;
            }
            if (RESID) {
                if (CO_T == 4) {
                    float4 r = *(const float4*)(resid + (size_t)n * CCH + resid_off + co0);
                    v[0] += r.x; v[1] += r.y; v[2] += r.z; v[3] += r.w;
                } else {
                    float2 r = *(const float2*)(resid + (size_t)n * CCH + resid_off + co0);
                    v[0] += r.x; v[1] += r.y;
                }
            }
            float* dst = fout + (size_t)n * out_stride + out_off + co0;
            if (CO_T == 4) {
                float4 st; st.x = v[0]; st.y = v[1]; st.z = v[2]; st.w = v[3];
                *(float4*)dst = st;
            } else {
                float2 st; st.x = v[0]; st.y = v[1];
                *(float2*)dst = st;
            }
        }
    }
}

// ---------- launch ----------
extern "C" void kernel_launch(void* const* d_in, const int* in_sizes, int n_in,
                              void* d_out, int out_size)
{
    const float* x    = (const float*)d_in[0];
    const int*   nbr  = (const int*)d_in[1];
    const int*   mask = (const int*)d_in[2];
    const float* W00 = (const float*)d_in[3];
    const float* b00 = (const float*)d_in[4];
    const float* W01 = (const float*)d_in[5];
    const float* b01 = (const float*)d_in[6];
    const float* W02 = (const float*)d_in[7];
    const float* b02 = (const float*)d_in[8];
    const float* W10 = (const float*)d_in[9];
    const float* b10 = (const float*)d_in[10];
    const float* W11 = (const float*)d_in[11];
    const float* b11 = (const float*)d_in[12];
    float* out = (float*)d_out;

    const int npts    = in_sizes[0] / CCH;
    const int grid128 = (npts + 127) / 128;
    const int grid64  = (npts + 63) / 64;

    float *h0p, *t0p, *h1p, *wb00, *wb01, *wb10, *wb11;
    cudaGetSymbolAddress((void**)&h0p,  g_h0);
    cudaGetSymbolAddress((void**)&t0p,  g_t0);
    cudaGetSymbolAddress((void**)&h1p,  g_h1);
    cudaGetSymbolAddress((void**)&wb00, g_wb00);
    cudaGetSymbolAddress((void**)&wb01, g_wb01);
    cudaGetSymbolAddress((void**)&wb10, g_wb10);
    cudaGetSymbolAddress((void**)&wb11, g_wb11);

    prep_wb<<<64, 256>>>(W00, wb00, 1,     CCH, C4);
    prep_wb<<<64, 256>>>(W01, wb01, KTAPS, C4,  C4);
    prep_wb<<<64, 256>>>(W10, wb10, KTAPS, CCH, C4);
    prep_wb<<<64, 256>>>(W11, wb11, KTAPS, C4,  C2);

    // SMEM: WARPS * NBUF * 16*36 floats
    const int smem_s1 = 8 * 3 * 576 * 4;   // 55296
    const int smem_s2 = 8 * 4 * 576 * 4;   // 73728
    const int smem_s3 = 8 * 4 * 576 * 4;   // 73728
    const int smem_s5 = 4 * 4 * 576 * 4;   // 36864
    const int smem_d4 = (32 * 130 + 32 * 64) * 4;

    cudaFuncSetAttribute(conv_wa<128, 32, 1, 3, 8, true, true, true, false, true>,
                         cudaFuncAttributeMaxDynamicSharedMemorySize, smem_s1);
    cudaFuncSetAttribute(conv_wa<32, 32, KTAPS, 4, 8, false, false, true, false, false>,
                         cudaFuncAttributeMaxDynamicSharedMemorySize, smem_s2);
    cudaFuncSetAttribute(conv_wa<128, 32, KTAPS, 4, 8, false, true, true, false, true>,
                         cudaFuncAttributeMaxDynamicSharedMemorySize, smem_s3);
    cudaFuncSetAttribute(conv_wa<32, 64, KTAPS, 4, 4, false, false, false, true, false>,
                         cudaFuncAttributeMaxDynamicSharedMemorySize, smem_s5);

    // 1) h0 = round(relu(x @ W00 + b00))           [dense, warp-autonomous]
    conv_wa<128, 32, 1, 3, 8, true, true, true, false, true><<<grid128, 256, smem_s1>>>(
        x, nullptr, nullptr, wb00, b00, h0p, C4, 0, nullptr, 0, npts);

    // 2) t0 = relu(conv3(h0, W01) + b01)           [32->32]
    conv_wa<32, 32, KTAPS, 4, 8, false, false, true, false, false><<<grid128, 256, smem_s2>>>(
        h0p, nbr, mask, wb01, b01, t0p, C4, 0, nullptr, 0, npts);

    // 3) h1 = round(relu(conv3(x, W10) + b10))     [128->32, cvt-A]
    conv_wa<128, 32, KTAPS, 4, 8, false, true, true, false, true><<<grid128, 256, smem_s3>>>(
        x, nbr, mask, wb10, b10, h1p, C4, 0, nullptr, 0, npts);

    // 4) out[:, 0:64] = t0 @ W02 + b02 + x[:, 0:64]   [FFMA2, full precision]
    conv1_kernel<32, 64, 128, false, true><<<grid128, 256, smem_d4>>>(
        t0p, W02, b02, out, CCH, 0, x, 0, npts);

    // 5) out[:, 64:128] = conv3(h1, W11) + b11 + x[:, 64:]  [32->64, 4-warp blocks]
    conv_wa<32, 64, KTAPS, 4, 4, false, false, false, true, false><<<grid64, 128, smem_s5>>>(
        h1p, nbr, mask, wb11, b11, out, CCH, 64, x, 64, npts);
}